// round 16
// baseline (speedup 1.0000x reference)
#include <cuda_runtime.h>
#include <cuda_fp16.h>
#include <math.h>

#define NN 100000
#define EE 3200000
#define ETOT 3300000   /* EE + NN self loops */
#define C1 256         /* HEADS*HD */
#define HD2 64
#define NEG 0.2f
#define NBLK_SCAN 98   /* ceil(NN/1024) */
#define MT1 6250       /* NN/16 m-tiles */
#define GB1 (MT1 / 2)  /* 3125 gemm blocks in fused kernel */
#define HB1 2048       /* hist blocks in fused kernel */

/* ---------------- scratch (device globals; no allocation allowed) -------- */
__device__ __half g_h1h[NN * C1];        /* layer1 features (fp16, row-major) */
__device__ float  g_as1[NN * 4];
__device__ float  g_ad1[NN * 4];
__device__ uint4  g_x2h4[NN * C1 / 8];   /* elu(agg1+b1) fp16 row-major       */
__device__ __half g_h2h[NN * HD2];       /* layer2 features (fp16)            */
__device__ float  g_as2[NN];
__device__ float  g_ad2[NN];
__device__ uint2  g_w1frag[4 * 8 * 8 * 32];  /* W1 in mma B-frag order */
__device__ uint2  g_w2frag[8 * 16 * 32];     /* W2 in mma B-frag order */
__device__ int    g_deg[NN];                 /* invariant: zero at entry */
__device__ int    g_rowptr[NN + 1];
__device__ int    g_cur[NN];
__device__ int    g_srcs[ETOT];
__device__ int    g_bsum[NBLK_SCAN];

__device__ __forceinline__ unsigned packh2(float a, float b) {
    __half2 h = __floats2half2_rn(a, b);
    return *(unsigned*)&h;
}

__device__ __forceinline__ void mma16816(float c[4],
    unsigned a0, unsigned a1, unsigned a2, unsigned a3,
    unsigned b0, unsigned b1) {
    asm volatile(
        "mma.sync.aligned.m16n8k16.row.col.f32.f16.f16.f32 "
        "{%0,%1,%2,%3}, {%4,%5,%6,%7}, {%8,%9}, {%0,%1,%2,%3};"
        : "+f"(c[0]), "+f"(c[1]), "+f"(c[2]), "+f"(c[3])
        : "r"(a0), "r"(a1), "r"(a2), "r"(a3), "r"(b0), "r"(b1));
}

/* per-block int64-vs-int32 edge dtype detection (odd 4B words all 0 => i64) */
__device__ __forceinline__ int block_is64(const int* __restrict__ ei32) {
    __shared__ int sflag;
    if (threadIdx.x == 0) sflag = 0;
    __syncthreads();
    if (threadIdx.x < 64 && ei32[2 * threadIdx.x + 1] != 0) sflag = 1;
    __syncthreads();
    return sflag == 0;
}

__device__ __forceinline__ int load_edge_cs(const void* ei, long long idx, int is64) {
    if (is64) return (int)__ldcs((const long long*)ei + idx);
    return __ldcs((const int*)ei + idx);
}

/* ---- fused GEMM1 + hist: blocks [0,GB1) do tensor GEMM, rest histogram -- */
#define STR1 136   /* padded halves per row: conflict-free fragment LDS */
__global__ void __launch_bounds__(256) k_gemm1hist(
    const float* __restrict__ x,
    const float* __restrict__ asw, const float* __restrict__ adw,
    const void* __restrict__ ei) {
    int t = threadIdx.x;

    if (blockIdx.x >= GB1) {
        /* ------- histogram portion, 4 independent edges per iteration ---- */
        int b = blockIdx.x - GB1;
        int is64 = block_is64((const int*)ei);
        const int stride = HB1 * 256;
        int base = b * 256 + t;
        for (int e = base; e < EE; e += 4 * stride) {
            int d0 = -1, d1 = -1, d2 = -1, d3 = -1;
            long long e1 = (long long)e + stride;
            long long e2 = (long long)e + 2 * stride;
            long long e3 = (long long)e + 3 * stride;
            d0 = load_edge_cs(ei, (long long)EE + e, is64);
            if (e1 < EE) d1 = load_edge_cs(ei, EE + e1, is64);
            if (e2 < EE) d2 = load_edge_cs(ei, EE + e2, is64);
            if (e3 < EE) d3 = load_edge_cs(ei, EE + e3, is64);
            atomicAdd(&g_deg[d0], 1);
            if (d1 >= 0) atomicAdd(&g_deg[d1], 1);
            if (d2 >= 0) atomicAdd(&g_deg[d2], 1);
            if (d3 >= 0) atomicAdd(&g_deg[d3], 1);
        }
        return;
    }

    /* ---------------- GEMM portion ---------------------------------- */
    __shared__ __half sx[2][16 * STR1];

    const float4* xg = (const float4*)(x + (long long)blockIdx.x * 32 * 128);
#pragma unroll
    for (int i = 0; i < 4; i++) {
        int f = t + i * 256;
        int r = f >> 5;
        int c4 = f & 31;
        float4 v = __ldcs(&xg[f]);
        __half* dst = &sx[r >> 4][(r & 15) * STR1 + c4 * 4];
        *(unsigned*)dst       = packh2(v.x, v.y);
        *(unsigned*)(dst + 2) = packh2(v.z, v.w);
    }
    __syncthreads();

    int w = t >> 5, l = t & 31;
    int hb = w >> 2;
    int mt = blockIdx.x * 2 + hb;
    int nw = w & 3;
    const __half* tile = sx[hb];
    int lr0 = l >> 2, lr1 = lr0 + 8;
    int cb = (l & 3) * 2;

    float c[8][4];
#pragma unroll
    for (int nt = 0; nt < 8; nt++)
#pragma unroll
        for (int j = 0; j < 4; j++) c[nt][j] = 0.f;

    const uint2* bf = g_w1frag + nw * 64 * 32 + l;
#pragma unroll
    for (int ks = 0; ks < 8; ks++) {
        int kb = ks * 16 + cb;
        unsigned ax = *(const unsigned*)&tile[lr0 * STR1 + kb];
        unsigned ay = *(const unsigned*)&tile[lr1 * STR1 + kb];
        unsigned az = *(const unsigned*)&tile[lr0 * STR1 + kb + 8];
        unsigned aw = *(const unsigned*)&tile[lr1 * STR1 + kb + 8];
#pragma unroll
        for (int nt = 0; nt < 8; nt++) {
            uint2 b = bf[(nt * 8 + ks) * 32];
            mma16816(c[nt], ax, ay, az, aw, b.x, b.y);
        }
    }

    int r0 = mt * 16 + lr0, r1 = r0 + 8;
    float ps0 = 0.f, ps1 = 0.f, pd0 = 0.f, pd1 = 0.f;
#pragma unroll
    for (int nt = 0; nt < 8; nt++) {
        int n = nw * 64 + nt * 8 + cb;
        *(unsigned*)&g_h1h[(long long)r0 * C1 + n] = packh2(c[nt][0], c[nt][1]);
        *(unsigned*)&g_h1h[(long long)r1 * C1 + n] = packh2(c[nt][2], c[nt][3]);
        float2 av = *(const float2*)&asw[n];
        float2 dv = *(const float2*)&adw[n];
        ps0 += c[nt][0] * av.x + c[nt][1] * av.y;
        ps1 += c[nt][2] * av.x + c[nt][3] * av.y;
        pd0 += c[nt][0] * dv.x + c[nt][1] * dv.y;
        pd1 += c[nt][2] * dv.x + c[nt][3] * dv.y;
    }
#pragma unroll
    for (int off = 1; off < 4; off <<= 1) {
        ps0 += __shfl_xor_sync(0xffffffffu, ps0, off);
        ps1 += __shfl_xor_sync(0xffffffffu, ps1, off);
        pd0 += __shfl_xor_sync(0xffffffffu, pd0, off);
        pd1 += __shfl_xor_sync(0xffffffffu, pd1, off);
    }
    if ((l & 3) == 0) {
        g_as1[r0 * 4 + nw] = ps0;
        g_as1[r1 * 4 + nw] = ps1;
        g_ad1[r0 * 4 + nw] = pd0;
        g_ad1[r1 * 4 + nw] = pd1;
    }
}

/* ---------------- CSR scans (self-loop +1 folded in) --------------------- */
__global__ void k_scan1() {
    __shared__ int sh[1024];
    int t = threadIdx.x;
    int i = blockIdx.x * 1024 + t;
    sh[t] = (i < NN) ? (g_deg[i] + 1) : 0;   /* +1: self loop */
    __syncthreads();
    for (int off = 512; off; off >>= 1) {
        if (t < off) sh[t] += sh[t + off];
        __syncthreads();
    }
    if (t == 0) g_bsum[blockIdx.x] = sh[0];
}

/* per-element scan; each block derives its own prefix of the 98 block sums */
__global__ void k_scan3() {
    __shared__ int sh[1024];
    __shared__ int wred[4];
    int t = threadIdx.x;
    int bid = blockIdx.x;

    if (t < 128) {
        int p = (t < bid) ? g_bsum[t] : 0;   /* bid <= 97 < 128 */
#pragma unroll
        for (int off = 16; off; off >>= 1)
            p += __shfl_xor_sync(0xffffffffu, p, off);
        if ((t & 31) == 0) wred[t >> 5] = p;
    }

    int i = bid * 1024 + t;
    int v = (i < NN) ? (g_deg[i] + 1) : 0;   /* +1: self loop */
    sh[t] = v;
    __syncthreads();
    int base = wred[0] + wred[1] + wred[2] + wred[3];
    for (int off = 1; off < 1024; off <<= 1) {
        int a = (t >= off) ? sh[t - off] : 0;
        __syncthreads();
        sh[t] += a;
        __syncthreads();
    }
    int excl = sh[t] - v + base;
    if (i < NN) {
        g_rowptr[i] = excl;
        g_cur[i] = excl;
        g_deg[i] = 0;           /* restore zero-at-entry invariant */
    }
    if (bid == 0 && t == 0) g_rowptr[NN] = ETOT;
}

/* scatter with 4 independent edge chains per iteration (MLP) */
__global__ void k_scatter(const void* __restrict__ ei) {
    int is64 = block_is64((const int*)ei);
    const int stride = 2048 * 256;
    int base = blockIdx.x * blockDim.x + threadIdx.x;
    for (int e = base; e < ETOT; e += 4 * stride) {
        long long ej[4];
        int s[4], d[4], valid[4];
#pragma unroll
        for (int j = 0; j < 4; j++) {
            ej[j] = (long long)e + (long long)j * stride;
            valid[j] = ej[j] < ETOT;
        }
#pragma unroll
        for (int j = 0; j < 4; j++) {
            if (valid[j]) {
                if (ej[j] < EE) {
                    s[j] = load_edge_cs(ei, ej[j], is64);
                    d[j] = load_edge_cs(ei, EE + ej[j], is64);
                } else {
                    s[j] = d[j] = (int)(ej[j] - EE);
                }
            }
        }
        int pos[4];
#pragma unroll
        for (int j = 0; j < 4; j++)
            if (valid[j]) pos[j] = atomicAdd(&g_cur[d[j]], 1);
#pragma unroll
        for (int j = 0; j < 4; j++)
            if (valid[j]) __stcs(&g_srcs[pos[j]], s[j]);
    }
}

/* ---------------- weight prep (W1+W2 -> fp16 B-fragment order) ----------- */
__global__ void __launch_bounds__(256) k_prep_w12(
    const float* __restrict__ W1, const float* __restrict__ W2) {
    int t = blockIdx.x * 256 + threadIdx.x;
    if (t < 8192) {
        int l = t & 31;
        int ks = (t >> 5) & 7;
        int nt = (t >> 8) & 7;
        int nw = t >> 11;
        int n = nw * 64 + nt * 8 + (l >> 2);
        int k0 = ks * 16 + (l & 3) * 2;
        uint2 v;
        v.x = packh2(W1[k0 * 256 + n],       W1[(k0 + 1) * 256 + n]);
        v.y = packh2(W1[(k0 + 8) * 256 + n], W1[(k0 + 9) * 256 + n]);
        g_w1frag[t] = v;
    } else {
        int t2 = t - 8192;
        int l = t2 & 31;
        int ks = (t2 >> 5) & 15;
        int nt = t2 >> 9;
        int n = nt * 8 + (l >> 2);
        int k0 = ks * 16 + (l & 3) * 2;
        uint2 v;
        v.x = packh2(W2[k0 * 64 + n],       W2[(k0 + 1) * 64 + n]);
        v.y = packh2(W2[(k0 + 8) * 64 + n], W2[(k0 + 9) * 64 + n]);
        g_w2frag[t2] = v;
    }
}

/* ---------------- GEMM2 (tensor, fused x2 staging): h2 = x2@W2 + alpha --- */
#define STR2 264   /* padded halves per row */
__global__ void __launch_bounds__(128) k_tgemm2(
    const float* __restrict__ asw, const float* __restrict__ adw) {
    __shared__ __half sx[4][16 * STR2];
    int t = threadIdx.x;

    long long gbase = (long long)blockIdx.x * 2048;
#pragma unroll
    for (int i = 0; i < 16; i++) {
        int g = t + i * 128;
        long long gi = gbase + g;
        uint4 v = (gi < (long long)NN * 32) ? __ldcs(&g_x2h4[gi])
                                            : make_uint4(0, 0, 0, 0);
        int ti = g >> 9;
        int rr = (g >> 5) & 15;
        int c8 = g & 31;
        __half* dst = &sx[ti][rr * STR2 + c8 * 8];
        *(uint2*)dst       = make_uint2(v.x, v.y);
        *(uint2*)(dst + 4) = make_uint2(v.z, v.w);
    }
    __syncthreads();

    int w = t >> 5, l = t & 31;
    int mt = blockIdx.x * 4 + w;
    const __half* tile = sx[w];
    int lr0 = l >> 2, lr1 = lr0 + 8;
    int cb = (l & 3) * 2;

    float c[8][4];
#pragma unroll
    for (int nt = 0; nt < 8; nt++)
#pragma unroll
        for (int j = 0; j < 4; j++) c[nt][j] = 0.f;

    const uint2* bf = g_w2frag + l;
#pragma unroll
    for (int ks = 0; ks < 16; ks++) {
        int kb = ks * 16 + cb;
        unsigned ax = *(const unsigned*)&tile[lr0 * STR2 + kb];
        unsigned ay = *(const unsigned*)&tile[lr1 * STR2 + kb];
        unsigned az = *(const unsigned*)&tile[lr0 * STR2 + kb + 8];
        unsigned aw = *(const unsigned*)&tile[lr1 * STR2 + kb + 8];
#pragma unroll
        for (int nt = 0; nt < 8; nt++) {
            uint2 b = bf[(nt * 16 + ks) * 32];
            mma16816(c[nt], ax, ay, az, aw, b.x, b.y);
        }
    }

    if (mt >= MT1) return;
    int r0 = mt * 16 + lr0, r1 = r0 + 8;
    float ps0 = 0.f, ps1 = 0.f, pd0 = 0.f, pd1 = 0.f;
#pragma unroll
    for (int nt = 0; nt < 8; nt++) {
        int n = nt * 8 + cb;
        *(unsigned*)&g_h2h[(long long)r0 * HD2 + n] = packh2(c[nt][0], c[nt][1]);
        *(unsigned*)&g_h2h[(long long)r1 * HD2 + n] = packh2(c[nt][2], c[nt][3]);
        float2 av = *(const float2*)&asw[n];
        float2 dv = *(const float2*)&adw[n];
        ps0 += c[nt][0] * av.x + c[nt][1] * av.y;
        ps1 += c[nt][2] * av.x + c[nt][3] * av.y;
        pd0 += c[nt][0] * dv.x + c[nt][1] * dv.y;
        pd1 += c[nt][2] * dv.x + c[nt][3] * dv.y;
    }
#pragma unroll
    for (int off = 1; off < 4; off <<= 1) {
        ps0 += __shfl_xor_sync(0xffffffffu, ps0, off);
        ps1 += __shfl_xor_sync(0xffffffffu, ps1, off);
        pd0 += __shfl_xor_sync(0xffffffffu, pd0, off);
        pd1 += __shfl_xor_sync(0xffffffffu, pd1, off);
    }
    if ((l & 3) == 0) {
        g_as2[r0] = ps0;
        g_as2[r1] = ps1;
        g_ad2[r0] = pd0;
        g_ad2[r1] = pd1;
    }
}

/* -------- aggregation layer 1: warp/node, single fused pass -------------- */
__global__ void __launch_bounds__(256) k_agg1(const float* __restrict__ b1) {
    int gw = (blockIdx.x * blockDim.x + threadIdx.x) >> 5;
    int lane = threadIdx.x & 31;
    if (gw >= NN) return;
    int n = gw;
    int beg = g_rowptr[n], end = g_rowptr[n + 1];

    int hh = lane >> 3;
    float adh = g_ad1[n * 4 + hh];
    int col = lane * 8;

    float A[8];
#pragma unroll
    for (int j = 0; j < 8; j++) A[j] = 0.f;
    float S = 0.f;

    int i = beg;
    for (; i + 3 < end; i += 4) {
        int s0 = __ldcs(&g_srcs[i]);
        int s1 = __ldcs(&g_srcs[i + 1]);
        int s2 = __ldcs(&g_srcs[i + 2]);
        int s3 = __ldcs(&g_srcs[i + 3]);
        float a0s = g_as1[s0 * 4 + hh];
        float a1s = g_as1[s1 * 4 + hh];
        float a2s = g_as1[s2 * 4 + hh];
        float a3s = g_as1[s3 * 4 + hh];
        uint4 u0 = *(const uint4*)&g_h1h[(long long)s0 * C1 + col];
        uint4 u1 = *(const uint4*)&g_h1h[(long long)s1 * C1 + col];
        uint4 u2 = *(const uint4*)&g_h1h[(long long)s2 * C1 + col];
        uint4 u3 = *(const uint4*)&g_h1h[(long long)s3 * C1 + col];
        float e0 = a0s + adh; e0 = e0 > 0.f ? e0 : NEG * e0;
        float e1 = a1s + adh; e1 = e1 > 0.f ? e1 : NEG * e1;
        float e2 = a2s + adh; e2 = e2 > 0.f ? e2 : NEG * e2;
        float e3 = a3s + adh; e3 = e3 > 0.f ? e3 : NEG * e3;
        float al0 = __expf(e0);
        float al1 = __expf(e1);
        float al2 = __expf(e2);
        float al3 = __expf(e3);
        S += al0 + al1 + al2 + al3;
        float2 f;
        f = __half22float2(*(__half2*)&u0.x); A[0] += al0 * f.x; A[1] += al0 * f.y;
        f = __half22float2(*(__half2*)&u0.y); A[2] += al0 * f.x; A[3] += al0 * f.y;
        f = __half22float2(*(__half2*)&u0.z); A[4] += al0 * f.x; A[5] += al0 * f.y;
        f = __half22float2(*(__half2*)&u0.w); A[6] += al0 * f.x; A[7] += al0 * f.y;
        f = __half22float2(*(__half2*)&u1.x); A[0] += al1 * f.x; A[1] += al1 * f.y;
        f = __half22float2(*(__half2*)&u1.y); A[2] += al1 * f.x; A[3] += al1 * f.y;
        f = __half22float2(*(__half2*)&u1.z); A[4] += al1 * f.x; A[5] += al1 * f.y;
        f = __half22float2(*(__half2*)&u1.w); A[6] += al1 * f.x; A[7] += al1 * f.y;
        f = __half22float2(*(__half2*)&u2.x); A[0] += al2 * f.x; A[1] += al2 * f.y;
        f = __half22float2(*(__half2*)&u2.y); A[2] += al2 * f.x; A[3] += al2 * f.y;
        f = __half22float2(*(__half2*)&u2.z); A[4] += al2 * f.x; A[5] += al2 * f.y;
        f = __half22float2(*(__half2*)&u2.w); A[6] += al2 * f.x; A[7] += al2 * f.y;
        f = __half22float2(*(__half2*)&u3.x); A[0] += al3 * f.x; A[1] += al3 * f.y;
        f = __half22float2(*(__half2*)&u3.y); A[2] += al3 * f.x; A[3] += al3 * f.y;
        f = __half22float2(*(__half2*)&u3.z); A[4] += al3 * f.x; A[5] += al3 * f.y;
        f = __half22float2(*(__half2*)&u3.w); A[6] += al3 * f.x; A[7] += al3 * f.y;
    }
    for (; i < end; i++) {
        int s0 = __ldcs(&g_srcs[i]);
        float a0s = g_as1[s0 * 4 + hh];
        uint4 u0 = *(const uint4*)&g_h1h[(long long)s0 * C1 + col];
        float e0 = a0s + adh; e0 = e0 > 0.f ? e0 : NEG * e0;
        float al0 = __expf(e0);
        S += al0;
        float2 f;
        f = __half22float2(*(__half2*)&u0.x); A[0] += al0 * f.x; A[1] += al0 * f.y;
        f = __half22float2(*(__half2*)&u0.y); A[2] += al0 * f.x; A[3] += al0 * f.y;
        f = __half22float2(*(__half2*)&u0.z); A[4] += al0 * f.x; A[5] += al0 * f.y;
        f = __half22float2(*(__half2*)&u0.w); A[6] += al0 * f.x; A[7] += al0 * f.y;
    }

    float inv = 1.f / S;

    float4 bb0 = *(const float4*)&b1[col];
    float4 bb1 = *(const float4*)&b1[col + 4];
    float o[8];
    o[0] = A[0] * inv + bb0.x; o[1] = A[1] * inv + bb0.y;
    o[2] = A[2] * inv + bb0.z; o[3] = A[3] * inv + bb0.w;
    o[4] = A[4] * inv + bb1.x; o[5] = A[5] * inv + bb1.y;
    o[6] = A[6] * inv + bb1.z; o[7] = A[7] * inv + bb1.w;
#pragma unroll
    for (int j = 0; j < 8; j++) o[j] = o[j] > 0.f ? o[j] : expm1f(o[j]);
    uint4 pk;
    pk.x = packh2(o[0], o[1]);
    pk.y = packh2(o[2], o[3]);
    pk.z = packh2(o[4], o[5]);
    pk.w = packh2(o[6], o[7]);
    __stcs(&g_x2h4[((long long)n * C1 + col) / 8], pk);
}

/* -------- aggregation layer 2 + final linear, single fused pass ---------- */
__global__ void __launch_bounds__(256) k_agg2(
    const float* __restrict__ b2, const float* __restrict__ lw,
    const float* __restrict__ lb, float* __restrict__ out) {
    int gw = (blockIdx.x * blockDim.x + threadIdx.x) >> 5;
    int lane = threadIdx.x & 31;
    if (gw >= NN) return;
    int n = gw;
    int beg = g_rowptr[n], end = g_rowptr[n + 1];
    float adn = g_ad2[n];

    int col = lane * 2;
    float a0 = 0.f, a1 = 0.f, S = 0.f;
    int i = beg;
    for (; i + 3 < end; i += 4) {
        int s0 = __ldcs(&g_srcs[i]);
        int s1 = __ldcs(&g_srcs[i + 1]);
        int s2 = __ldcs(&g_srcs[i + 2]);
        int s3 = __ldcs(&g_srcs[i + 3]);
        float e0 = g_as2[s0] + adn;
        float e1 = g_as2[s1] + adn;
        float e2 = g_as2[s2] + adn;
        float e3 = g_as2[s3] + adn;
        __half2 v0h = *(const __half2*)&g_h2h[(long long)s0 * HD2 + col];
        __half2 v1h = *(const __half2*)&g_h2h[(long long)s1 * HD2 + col];
        __half2 v2h = *(const __half2*)&g_h2h[(long long)s2 * HD2 + col];
        __half2 v3h = *(const __half2*)&g_h2h[(long long)s3 * HD2 + col];
        e0 = e0 > 0.f ? e0 : NEG * e0;
        e1 = e1 > 0.f ? e1 : NEG * e1;
        e2 = e2 > 0.f ? e2 : NEG * e2;
        e3 = e3 > 0.f ? e3 : NEG * e3;
        float al0 = __expf(e0);
        float al1 = __expf(e1);
        float al2 = __expf(e2);
        float al3 = __expf(e3);
        S += al0 + al1 + al2 + al3;
        float2 v0 = __half22float2(v0h);
        float2 v1 = __half22float2(v1h);
        float2 v2 = __half22float2(v2h);
        float2 v3 = __half22float2(v3h);
        a0 += al0 * v0.x + al1 * v1.x + al2 * v2.x + al3 * v3.x;
        a1 += al0 * v0.y + al1 * v1.y + al2 * v2.y + al3 * v3.y;
    }
    for (; i < end; i++) {
        int s0 = __ldcs(&g_srcs[i]);
        float e0 = g_as2[s0] + adn;
        __half2 v0h = *(const __half2*)&g_h2h[(long long)s0 * HD2 + col];
        float2 v0 = __half22float2(v0h);
        e0 = e0 > 0.f ? e0 : NEG * e0;
        float al0 = __expf(e0);
        S += al0;
        a0 += al0 * v0.x;
        a1 += al0 * v0.y;
    }
    float inv = 1.f / S;

    float v0 = a0 * inv + b2[col];     v0 = v0 > 0.f ? v0 : expm1f(v0);
    float v1 = a1 * inv + b2[col + 1]; v1 = v1 > 0.f ? v1 : expm1f(v1);
    float p0 = v0 * lw[col * 2 + 0] + v1 * lw[(col + 1) * 2 + 0];
    float p1 = v0 * lw[col * 2 + 1] + v1 * lw[(col + 1) * 2 + 1];
#pragma unroll
    for (int off = 16; off; off >>= 1) {
        p0 += __shfl_down_sync(0xffffffffu, p0, off);
        p1 += __shfl_down_sync(0xffffffffu, p1, off);
    }
    if (lane == 0) {
        out[n * 2 + 0] = p0 + lb[0];
        out[n * 2 + 1] = p1 + lb[1];
    }
}

/* ---------------- launcher -------------------------------------------- */
extern "C" void kernel_launch(void* const* d_in, const int* in_sizes, int n_in,
                              void* d_out, int out_size) {
    const float* x   = (const float*)d_in[0];
    const void*  ei  = d_in[1];
    const float* W1  = (const float*)d_in[2];
    const float* as1 = (const float*)d_in[3];
    const float* ad1 = (const float*)d_in[4];
    const float* b1  = (const float*)d_in[5];
    const float* W2  = (const float*)d_in[6];
    const float* as2 = (const float*)d_in[7];
    const float* ad2 = (const float*)d_in[8];
    const float* b2  = (const float*)d_in[9];
    const float* lw  = (const float*)d_in[10];
    const float* lb  = (const float*)d_in[11];
    float* out = (float*)d_out;

    k_prep_w12<<<48, 256>>>(W1, W2);
    k_gemm1hist<<<GB1 + HB1, 256>>>(x, as1, ad1, ei);  /* gemm + hist overlap */
    k_scan1<<<NBLK_SCAN, 1024>>>();
    k_scan3<<<NBLK_SCAN, 1024>>>();                    /* inline bsum prefix  */
    k_scatter<<<2048, 256>>>(ei);

    k_agg1<<<(NN * 32 + 255) / 256, 256>>>(b1);
    k_tgemm2<<<(MT1 + 3) / 4, 128>>>(as2, ad2);
    k_agg2<<<(NN * 32 + 255) / 256, 256>>>(b2, lw, lb, out);
}